// round 14
// baseline (speedup 1.0000x reference)
#include <cuda_runtime.h>
#include <math.h>

#define DEVHOST __host__ __device__
typedef unsigned long long u64;

// ------------------------- compile-time structure -------------------------
DEVHOST constexpr int kTL (int i){ const int a[23]={0,0,0,0, 1,1,1,1,1,1, 2,2,2,2,2,2,2, 3,3,3,3,3,3}; return a[i]; }
DEVHOST constexpr int kTL1(int i){ const int a[23]={0,1,2,3, 1,1,2,2,3,3, 1,2,2,2,3,3,3, 2,2,3,3,3,3}; return a[i]; }
DEVHOST constexpr int kTL2(int i){ const int a[23]={0,1,2,3, 0,1,1,2,2,3, 1,0,1,2,1,2,3, 1,2,0,1,2,3}; return a[i]; }

DEVHOST constexpr int imax2(int a,int b){ return a>b?a:b; }
DEVHOST constexpr int imin2(int a,int b){ return a<b?a:b; }
DEVHOST constexpr int ilo_c(int l1,int l2,int m){ return imax2(-l1, m-l2); }
DEVHOST constexpr int ihi_c(int l1,int l2,int m){ return imin2( l1, m+l2); }
DEVHOST constexpr int rown_c(int l1,int l2,int m){ return ihi_c(l1,l2,m)-ilo_c(l1,l2,m)+1; }

DEVHOST constexpr int kInOff(int l){ const int a[4]={0,16,64,144};        return a[l]; }
DEVHOST constexpr int kMLf  (int l){ const int a[4]={1024,1536,1792,1536}; return a[l]; }
DEVHOST constexpr int kTrip0(int l){ const int a[5]={0,4,10,17,23};        return a[l]; }
DEVHOST constexpr int kSOff (int l){ const int a[4]={0,1024,2560,4352};    return a[l]; }
DEVHOST constexpr int kWBase(int l){ const int a[4]={0,16384,40960,69632}; return a[l]; }

// ------------------- compile-time Clebsch-Gordan values -------------------
DEVHOST constexpr double dfact(int n){ double r=1.0; for(int i=2;i<=n;++i) r*=(double)i; return r; }
DEVHOST constexpr double csqrt(double x){
    double g = (x>1.0)?x:1.0;
    for(int i=0;i<64;++i) g = 0.5*(g + x/g);
    return g;
}
DEVHOST constexpr double cgcoef(int l1,int m1,int l2,int m2,int l,int m){
    double pre = csqrt((double)(2*l+1)*dfact(l1+l2-l)*dfact(l1-l2+l)*dfact(-l1+l2+l)/dfact(l1+l2+l+1));
    pre = pre * csqrt(dfact(l+m)*dfact(l-m)*dfact(l1-m1)*dfact(l1+m1)*dfact(l2-m2)*dfact(l2+m2));
    double s = 0.0;
    for(int k=0;k<=l1+l2-l;++k){
        int d0=k, d1=l1+l2-l-k, d2=l1-m1-k, d3=l2+m2-k, d4=l-l2+m1+k, d5=l-l1-m2+k;
        if(d0<0||d1<0||d2<0||d3<0||d4<0||d5<0) continue;
        double den = dfact(d0)*dfact(d1)*dfact(d2)*dfact(d3)*dfact(d4)*dfact(d5);
        s += ((k&1)? -1.0 : 1.0)/den;
    }
    return pre*s;
}

// ------------------------------ device scratch ----------------------------
static constexpr int NCH   = 5888;
static constexpr int NBLK1 = 512;
static constexpr u64 SGNMASK = 0x8000000080000000ULL;

__device__ float g_part[(long)NBLK1 * NCH];
__device__ float g_scale[NCH];
__device__ u64   g_wrr[94208];
__device__ u64   g_wii[94208];

// -------------------------------- f32x2 ops -------------------------------
__device__ __forceinline__ u64 pk2(float lo, float hi){
    u64 r; asm("mov.b64 %0,{%1,%2};" : "=l"(r) : "f"(lo), "f"(hi)); return r;
}
__device__ __forceinline__ void upk2(float& lo, float& hi, u64 v){
    asm("mov.b64 {%0,%1},%2;" : "=f"(lo), "=f"(hi) : "l"(v));
}
__device__ __forceinline__ u64 fma2(u64 a, u64 b, u64 c){
    u64 d; asm("fma.rn.f32x2 %0,%1,%2,%3;" : "=l"(d) : "l"(a), "l"(b), "l"(c)); return d;
}
__device__ __forceinline__ u64 add2(u64 a, u64 b){
    u64 d; asm("add.rn.f32x2 %0,%1,%2;" : "=l"(d) : "l"(a), "l"(b)); return d;
}
__device__ __forceinline__ u64 mul2(u64 a, u64 b){
    u64 d; asm("mul.rn.f32x2 %0,%1,%2;" : "=l"(d) : "l"(a), "l"(b)); return d;
}
__device__ __forceinline__ ulonglong2 ldg2(const u64* p){
    ulonglong2 v;
    asm("ld.global.nc.v2.u64 {%0,%1},[%2];" : "=l"(v.x), "=l"(v.y) : "l"(p));
    return v;
}

// ---------------- packed TP inner (2 batches in f32x2 lanes) ---------------
template<int TR,int P,int J,int N,int D1,int D2>
struct JL2 {
    static __device__ __forceinline__ void run(const u64 (&f1re)[D1], const u64 (&f1im)[D1],
                                               const u64 (&f2re)[D2], const u64 (&f2im)[D2],
                                               u64& ar2, u64& ai2){
        constexpr int L=kTL(TR), L1=kTL1(TR), L2=kTL2(TR);
        constexpr int M  = P - L;
        constexpr int M1 = ilo_c(L1,L2,M) + J;
        constexpr int M2 = M - M1;
        constexpr float v = (float)cgcoef(L1,M1,L2,M2,L,M);
        const u64 vv = pk2(v,v);
        u64 are = f1re[M1+L1], aim = f1im[M1+L1];
        u64 bre = f2re[M2+L2], bim = f2im[M2+L2];
        u64 aimn = aim ^ SGNMASK;
        u64 t1 = mul2(are,bre); t1 = fma2(aimn,bim,t1);
        ar2 = fma2(vv,t1,ar2);
        u64 t2 = mul2(are,bim); t2 = fma2(aim,bre,t2);
        ai2 = fma2(vv,t2,ai2);
        if constexpr (J+1 < N)
            JL2<TR,P,J+1,N,D1,D2>::run(f1re,f1im,f2re,f2im,ar2,ai2);
    }
};

// nsq variant
template<int TR,int P,int D1,int D2>
struct PL2n {
    static __device__ __forceinline__ void run(const u64 (&f1re)[D1], const u64 (&f1im)[D1],
                                               const u64 (&f2re)[D2], const u64 (&f2im)[D2],
                                               u64& nsq2){
        constexpr int L = kTL(TR);
        constexpr int N = rown_c(kTL1(TR),kTL2(TR),P-L);
        u64 ar2=0ULL, ai2=0ULL;
        JL2<TR,P,0,N,D1,D2>::run(f1re,f1im,f2re,f2im,ar2,ai2);
        nsq2 = fma2(ar2,ar2,nsq2);
        nsq2 = fma2(ai2,ai2,nsq2);
        if constexpr (P+1 < 2*L+1) PL2n<TR,P+1,D1,D2>::run(f1re,f1im,f2re,f2im,nsq2);
    }
};

// smem-store variant: op[p*256] = (ar2, ai2) as ulonglong2 (16B STS)
template<int TR,int P,int D1,int D2>
struct PL2s {
    static __device__ __forceinline__ void run(const u64 (&f1re)[D1], const u64 (&f1im)[D1],
                                               const u64 (&f2re)[D2], const u64 (&f2im)[D2],
                                               ulonglong2* op){
        constexpr int L = kTL(TR);
        constexpr int N = rown_c(kTL1(TR),kTL2(TR),P-L);
        u64 ar2=0ULL, ai2=0ULL;
        JL2<TR,P,0,N,D1,D2>::run(f1re,f1im,f2re,f2im,ar2,ai2);
        op[P*256] = make_ulonglong2(ar2, ai2);
        if constexpr (P+1 < 2*L+1) PL2s<TR,P+1,D1,D2>::run(f1re,f1im,f2re,f2im,op);
    }
};

// --------------------- k1': TP -> |mid|^2 partials only --------------------
// 256 threads, 4 batches per block packed as 2 pairs: j -> (b0+j, b0+j+2)
template<int TR>
__device__ __forceinline__ void do_tripn2(const u64* actp, int tid){
    constexpr int L1 = kTL1(TR), L2 = kTL2(TR);
    constexpr int D1 = 2*L1+1, D2 = 2*L2+1;
    const int t = tid>>4, s = tid&15;
    u64 nsq2 = 0ULL;
    #pragma unroll
    for (int j=0;j<2;++j){
        const u64* ap = actp + j*512;
        u64 f1re[D1], f1im[D1], f2re[D2], f2im[D2];
        #pragma unroll
        for (int i=0;i<D1;++i){
            int idx = (kInOff(L1) + t*D1 + i)*2;
            f1re[i] = ap[idx]; f1im[i] = ap[idx+1];
        }
        #pragma unroll
        for (int i=0;i<D2;++i){
            int idx = (kInOff(L2) + s*D2 + i)*2;
            f2re[i] = ap[idx]; f2im[i] = ap[idx+1];
        }
        PL2n<TR,0,D1,D2>::run(f1re,f1im,f2re,f2im,nsq2);
    }
    float lo,hi; upk2(lo,hi,nsq2);
    g_part[(long)blockIdx.x*NCH + TR*256 + tid] = lo + hi;
}

template<int TR>
struct TripsN2 {
    static __device__ __forceinline__ void run(const u64* actp, int tid){
        do_tripn2<TR>(actp,tid);
        if constexpr (TR+1 < 23) TripsN2<TR+1>::run(actp,tid);
    }
};

__global__ void __launch_bounds__(256) k1_kernel(const float* __restrict__ act){
    __shared__ u64 actp[2*512];
    const int tid = threadIdx.x;
    const int b0  = blockIdx.x*4;
    for (int idx=tid; idx<1024; idx+=256){
        int j = idx>>9, i = idx&511;
        actp[idx] = pk2(act[(long)(b0+j)*512 + i], act[(long)(b0+j+2)*512 + i]);
    }
    __syncthreads();
    TripsN2<0>::run(actp, tid);
}

// ------------- k2a: reduce partials -> inverse (new_std + eps) ------------
__global__ void k2a_kernel(const float* __restrict__ bn){
    int c = blockIdx.x*256 + threadIdx.x;
    if (c >= NCH) return;
    int l = (c<1024)?0:((c<2560)?1:((c<4352)?2:3));
    float s[8];
    #pragma unroll
    for (int j=0;j<8;++j) s[j]=0.f;
    for (int i=0;i<NBLK1;i+=8){
        #pragma unroll
        for (int j=0;j<8;++j) s[j] += g_part[(long)(i+j)*NCH + c];
    }
    float t = 0.f;
    #pragma unroll
    for (int j=0;j<8;++j) t += s[j];
    float bstd = sqrtf(t / (2048.0f * (float)(2*l+1)));
    g_scale[c] = 1.0f/(0.5f*(bn[c] + bstd) + 1e-5f);
}

// --------------- k2b: fold scale into W, duplicated lanes ------------------
__global__ void k2b_kernel(const float* __restrict__ W){
    int r = blockIdx.x*256 + threadIdx.x;
    if (r >= 94208) return;
    int l = (r<16384)?0:((r<40960)?1:((r<69632)?2:3));
    int rr = r - kWBase(l);
    int c  = rr % kMLf(l);
    float sc = g_scale[kSOff(l) + c];
    float wr = W[2*r]*sc, wi = W[2*r+1]*sc;
    g_wrr[r] = pk2(wr, wr);
    g_wii[r] = pk2(wi, wi);
}

// ---------------- k3f: fused TP-recompute + complex GEMM -------------------
// 512 threads, 8 batches (4 packed pairs: j -> (b0+j, b0+j+4)) x one l.
// phase A: packed TP -> smem [(pair, p, c) -> (re2, im2)]
// phase B: batch-packed GEMM; threads = cs(8, 2 ch) x o(16) x pair(4)
static constexpr int SMEM_MID_BYTES = 4*7*256*16;   // 114688
static constexpr int SMEM_ACT_OFF   = SMEM_MID_BYTES;
static constexpr int SMEM_TOTAL     = SMEM_MID_BYTES + 4*512*8; // 131072

template<int L,int TR>
__device__ __forceinline__ void phaseA2(const u64* actp, ulonglong2* smid, int tid){
    constexpr int L1 = kTL1(TR), L2 = kTL2(TR);
    constexpr int D1 = 2*L1+1, D2 = 2*L2+1;
    constexpr int DP = 2*L+1;
    const int ch   = tid & 255;
    const int t    = ch >> 4, s = ch & 15;
    const int half = tid >> 8;
    #pragma unroll
    for (int jj=0;jj<2;++jj){
        const int j = half*2 + jj;
        const u64* ap = actp + j*512;
        u64 f1re[D1], f1im[D1], f2re[D2], f2im[D2];
        #pragma unroll
        for (int i=0;i<D1;++i){
            int idx = (kInOff(L1) + t*D1 + i)*2;
            f1re[i] = ap[idx]; f1im[i] = ap[idx+1];
        }
        #pragma unroll
        for (int i=0;i<D2;++i){
            int idx = (kInOff(L2) + s*D2 + i)*2;
            f2re[i] = ap[idx]; f2im[i] = ap[idx+1];
        }
        PL2s<TR,0,D1,D2>::run(f1re,f1im,f2re,f2im, smid + (j*DP)*256 + ch);
    }
}

template<int L,int TR>
__device__ __forceinline__ void phaseB2(const ulonglong2* smid,
                                        u64 (&sA)[2*L+1], u64 (&sB)[2*L+1],
                                        u64 (&sC)[2*L+1], u64 (&sD)[2*L+1],
                                        int cs, int o, int pair){
    constexpr int DP = 2*L+1;
    constexpr int ML = kMLf(L);
    constexpr int WB = kWBase(L);
    constexpr int TB = (TR - kTrip0(L))*256;
    const ulonglong2* mbase = smid + pair*(DP*256);
    const u64* wrp = g_wrr + WB + (long)o*ML + TB;
    const u64* wip = g_wii + WB + (long)o*ML + TB;
    #pragma unroll 4
    for (int it=0; it<16; ++it){
        const int c = it*16 + cs*2;
        ulonglong2 wr = ldg2(wrp + c);   // (wrr[c], wrr[c+1])
        ulonglong2 wi = ldg2(wip + c);
        #pragma unroll
        for (int p=0;p<DP;++p){
            ulonglong2 m0 = mbase[p*256 + c];
            ulonglong2 m1 = mbase[p*256 + c + 1];
            sA[p] = fma2(wr.x, m0.x, sA[p]);
            sB[p] = fma2(wr.x, m0.y, sB[p]);
            sC[p] = fma2(wi.x, m0.x, sC[p]);
            sD[p] = fma2(wi.x, m0.y, sD[p]);
            sA[p] = fma2(wr.y, m1.x, sA[p]);
            sB[p] = fma2(wr.y, m1.y, sB[p]);
            sC[p] = fma2(wi.y, m1.x, sC[p]);
            sD[p] = fma2(wi.y, m1.y, sD[p]);
        }
    }
}

template<int L,int TR,int TREND>
struct TripF2 {
    static __device__ __forceinline__ void run(const u64* actp, ulonglong2* smid,
                                               u64 (&sA)[2*L+1], u64 (&sB)[2*L+1],
                                               u64 (&sC)[2*L+1], u64 (&sD)[2*L+1],
                                               int tid, int cs, int o, int pair){
        phaseA2<L,TR>(actp, smid, tid);
        __syncthreads();
        phaseB2<L,TR>(smid, sA,sB,sC,sD, cs, o, pair);
        __syncthreads();
        if constexpr (TR+1 < TREND)
            TripF2<L,TR+1,TREND>::run(actp,smid,sA,sB,sC,sD,tid,cs,o,pair);
    }
};

template<int L>
__device__ __forceinline__ void k3body(const float* __restrict__ act, float* __restrict__ out,
                                       int bg, char* sm){
    constexpr int DP   = 2*L+1;
    constexpr int OROW = kInOff(L);
    ulonglong2* smid = reinterpret_cast<ulonglong2*>(sm);
    u64*        actp = reinterpret_cast<u64*>(sm + SMEM_ACT_OFF);

    const int tid = threadIdx.x;
    const int b0  = bg*8;

    // pack 8 batches into 4 batch-pair lanes: j -> (b0+j, b0+j+4)
    for (int idx=tid; idx<2048; idx+=512){
        int j = idx>>9, i = idx&511;
        actp[idx] = pk2(act[(long)(b0+j)*512 + i], act[(long)(b0+j+4)*512 + i]);
    }
    __syncthreads();

    const int cs   = tid & 7;
    const int o    = (tid>>3) & 15;
    const int pair = tid >> 7;

    u64 sA[DP], sB[DP], sC[DP], sD[DP];
    #pragma unroll
    for (int p=0;p<DP;++p){ sA[p]=0ULL; sB[p]=0ULL; sC[p]=0ULL; sD[p]=0ULL; }

    TripF2<L, kTrip0(L), kTrip0(L+1)>::run(actp, smid, sA,sB,sC,sD, tid, cs, o, pair);

    // out_re2 = sA - sD ; out_im2 = sB + sC ; butterfly over cs (lane bits 0..2)
    u64 re2[DP], im2[DP];
    #pragma unroll
    for (int p=0;p<DP;++p){
        u64 r = add2(sA[p], sD[p] ^ SGNMASK);
        u64 m = add2(sB[p], sC[p]);
        r = add2(r, __shfl_xor_sync(0xffffffffu, r, 1));
        m = add2(m, __shfl_xor_sync(0xffffffffu, m, 1));
        r = add2(r, __shfl_xor_sync(0xffffffffu, r, 2));
        m = add2(m, __shfl_xor_sync(0xffffffffu, m, 2));
        r = add2(r, __shfl_xor_sync(0xffffffffu, r, 4));
        m = add2(m, __shfl_xor_sync(0xffffffffu, m, 4));
        re2[p]=r; im2[p]=m;
    }

    if (cs == 0){
        #pragma unroll
        for (int p=0;p<DP;++p){
            float ra,rb,ia,ib;
            upk2(ra,rb,re2[p]);
            upk2(ia,ib,im2[p]);
            long rowA = (long)(b0+pair)*256   + OROW + o*DP + p;
            long rowB = (long)(b0+pair+4)*256 + OROW + o*DP + p;
            reinterpret_cast<float2*>(out)[rowA] = make_float2(ra,ia);
            reinterpret_cast<float2*>(out)[rowB] = make_float2(rb,ib);
        }
    }
}

__global__ void __launch_bounds__(512,1) k3f_kernel(const float* __restrict__ act,
                                                    float* __restrict__ out){
    extern __shared__ char sm[];
    const int bid = blockIdx.x;
    const int li  = bid >> 8;       // 0..3, longest l first
    const int bg  = bid & 255;
    switch (li){
        case 0: k3body<3>(act,out,bg,sm); break;
        case 1: k3body<2>(act,out,bg,sm); break;
        case 2: k3body<1>(act,out,bg,sm); break;
        default: k3body<0>(act,out,bg,sm); break;
    }
}

// --------------------------------- launch ---------------------------------
extern "C" void kernel_launch(void* const* d_in, const int* in_sizes, int n_in,
                              void* d_out, int out_size){
    const float* act = nullptr;
    const float* W   = nullptr;
    const float* bn  = nullptr;
    for (int i=0;i<n_in;++i){
        if      (in_sizes[i] == 1048576) act = (const float*)d_in[i];
        else if (in_sizes[i] == 188416)  W   = (const float*)d_in[i];
        else if (in_sizes[i] == 5888)    bn  = (const float*)d_in[i];
    }
    float* out = (float*)d_out;

    static bool attr_set = false;
    if (!attr_set){
        cudaFuncSetAttribute(k3f_kernel, cudaFuncAttributeMaxDynamicSharedMemorySize, SMEM_TOTAL);
        attr_set = true;
    }

    k1_kernel<<<512,256>>>(act);
    k2a_kernel<<<23,256>>>(bn);
    k2b_kernel<<<368,256>>>(W);
    k3f_kernel<<<1024,512,SMEM_TOTAL>>>(act, out);
}

// round 16
// speedup vs baseline: 1.5634x; 1.5634x over previous
#include <cuda_runtime.h>
#include <math.h>

#define DEVHOST __host__ __device__
typedef unsigned long long u64;

// ------------------------- compile-time structure -------------------------
DEVHOST constexpr int kTL (int i){ const int a[23]={0,0,0,0, 1,1,1,1,1,1, 2,2,2,2,2,2,2, 3,3,3,3,3,3}; return a[i]; }
DEVHOST constexpr int kTL1(int i){ const int a[23]={0,1,2,3, 1,1,2,2,3,3, 1,2,2,2,3,3,3, 2,2,3,3,3,3}; return a[i]; }
DEVHOST constexpr int kTL2(int i){ const int a[23]={0,1,2,3, 0,1,1,2,2,3, 1,0,1,2,1,2,3, 1,2,0,1,2,3}; return a[i]; }

DEVHOST constexpr int imax2(int a,int b){ return a>b?a:b; }
DEVHOST constexpr int imin2(int a,int b){ return a<b?a:b; }
DEVHOST constexpr int ilo_c(int l1,int l2,int m){ return imax2(-l1, m-l2); }
DEVHOST constexpr int ihi_c(int l1,int l2,int m){ return imin2( l1, m+l2); }
DEVHOST constexpr int rown_c(int l1,int l2,int m){ return ihi_c(l1,l2,m)-ilo_c(l1,l2,m)+1; }

DEVHOST constexpr int kInOff(int l){ const int a[4]={0,16,64,144};        return a[l]; }
DEVHOST constexpr int kMLf  (int l){ const int a[4]={1024,1536,1792,1536}; return a[l]; }
DEVHOST constexpr int kTrip0(int l){ const int a[5]={0,4,10,17,23};        return a[l]; }
DEVHOST constexpr int kSOff (int l){ const int a[4]={0,1024,2560,4352};    return a[l]; }
DEVHOST constexpr int kWBase(int l){ const int a[4]={0,16384,40960,69632}; return a[l]; }

// ------------------- compile-time Clebsch-Gordan values -------------------
DEVHOST constexpr double dfact(int n){ double r=1.0; for(int i=2;i<=n;++i) r*=(double)i; return r; }
DEVHOST constexpr double csqrt(double x){
    double g = (x>1.0)?x:1.0;
    for(int i=0;i<64;++i) g = 0.5*(g + x/g);
    return g;
}
DEVHOST constexpr double cgcoef(int l1,int m1,int l2,int m2,int l,int m){
    double pre = csqrt((double)(2*l+1)*dfact(l1+l2-l)*dfact(l1-l2+l)*dfact(-l1+l2+l)/dfact(l1+l2+l+1));
    pre = pre * csqrt(dfact(l+m)*dfact(l-m)*dfact(l1-m1)*dfact(l1+m1)*dfact(l2-m2)*dfact(l2+m2));
    double s = 0.0;
    for(int k=0;k<=l1+l2-l;++k){
        int d0=k, d1=l1+l2-l-k, d2=l1-m1-k, d3=l2+m2-k, d4=l-l2+m1+k, d5=l-l1-m2+k;
        if(d0<0||d1<0||d2<0||d3<0||d4<0||d5<0) continue;
        double den = dfact(d0)*dfact(d1)*dfact(d2)*dfact(d3)*dfact(d4)*dfact(d5);
        s += ((k&1)? -1.0 : 1.0)/den;
    }
    return pre*s;
}

// ------------------------------ device scratch ----------------------------
static constexpr int NCH   = 5888;
static constexpr int NBLK1 = 512;
static constexpr u64 SGNMASK = 0x8000000080000000ULL;

__device__ float g_part[(long)NBLK1 * NCH];
__device__ float g_scale[NCH];
__device__ u64   g_wrr[94208];
__device__ u64   g_wii[94208];

// -------------------------------- f32x2 ops -------------------------------
__device__ __forceinline__ u64 pk2(float lo, float hi){
    u64 r; asm("mov.b64 %0,{%1,%2};" : "=l"(r) : "f"(lo), "f"(hi)); return r;
}
__device__ __forceinline__ void upk2(float& lo, float& hi, u64 v){
    asm("mov.b64 {%0,%1},%2;" : "=f"(lo), "=f"(hi) : "l"(v));
}
__device__ __forceinline__ u64 fma2(u64 a, u64 b, u64 c){
    u64 d; asm("fma.rn.f32x2 %0,%1,%2,%3;" : "=l"(d) : "l"(a), "l"(b), "l"(c)); return d;
}
__device__ __forceinline__ u64 add2(u64 a, u64 b){
    u64 d; asm("add.rn.f32x2 %0,%1,%2;" : "=l"(d) : "l"(a), "l"(b)); return d;
}
__device__ __forceinline__ u64 mul2(u64 a, u64 b){
    u64 d; asm("mul.rn.f32x2 %0,%1,%2;" : "=l"(d) : "l"(a), "l"(b)); return d;
}
__device__ __forceinline__ u64 ldg8(const u64* p){
    u64 v; asm("ld.global.nc.u64 %0,[%1];" : "=l"(v) : "l"(p)); return v;
}

// ---------------- packed TP inner (2 batches in f32x2 lanes) ---------------
template<int TR,int P,int J,int N,int D1,int D2>
struct JL2 {
    static __device__ __forceinline__ void run(const u64 (&f1re)[D1], const u64 (&f1im)[D1],
                                               const u64 (&f2re)[D2], const u64 (&f2im)[D2],
                                               u64& ar2, u64& ai2){
        constexpr int L=kTL(TR), L1=kTL1(TR), L2=kTL2(TR);
        constexpr int M  = P - L;
        constexpr int M1 = ilo_c(L1,L2,M) + J;
        constexpr int M2 = M - M1;
        constexpr float v = (float)cgcoef(L1,M1,L2,M2,L,M);
        const u64 vv = pk2(v,v);
        u64 are = f1re[M1+L1], aim = f1im[M1+L1];
        u64 bre = f2re[M2+L2], bim = f2im[M2+L2];
        u64 aimn = aim ^ SGNMASK;
        u64 t1 = mul2(are,bre); t1 = fma2(aimn,bim,t1);
        ar2 = fma2(vv,t1,ar2);
        u64 t2 = mul2(are,bim); t2 = fma2(aim,bre,t2);
        ai2 = fma2(vv,t2,ai2);
        if constexpr (J+1 < N)
            JL2<TR,P,J+1,N,D1,D2>::run(f1re,f1im,f2re,f2im,ar2,ai2);
    }
};

// nsq variant
template<int TR,int P,int D1,int D2>
struct PL2n {
    static __device__ __forceinline__ void run(const u64 (&f1re)[D1], const u64 (&f1im)[D1],
                                               const u64 (&f2re)[D2], const u64 (&f2im)[D2],
                                               u64& nsq2){
        constexpr int L = kTL(TR);
        constexpr int N = rown_c(kTL1(TR),kTL2(TR),P-L);
        u64 ar2=0ULL, ai2=0ULL;
        JL2<TR,P,0,N,D1,D2>::run(f1re,f1im,f2re,f2im,ar2,ai2);
        nsq2 = fma2(ar2,ar2,nsq2);
        nsq2 = fma2(ai2,ai2,nsq2);
        if constexpr (P+1 < 2*L+1) PL2n<TR,P+1,D1,D2>::run(f1re,f1im,f2re,f2im,nsq2);
    }
};

// smem-store variant: op[p*256] = (ar2, ai2) as ulonglong2 (16B STS)
template<int TR,int P,int D1,int D2>
struct PL2s {
    static __device__ __forceinline__ void run(const u64 (&f1re)[D1], const u64 (&f1im)[D1],
                                               const u64 (&f2re)[D2], const u64 (&f2im)[D2],
                                               ulonglong2* op){
        constexpr int L = kTL(TR);
        constexpr int N = rown_c(kTL1(TR),kTL2(TR),P-L);
        u64 ar2=0ULL, ai2=0ULL;
        JL2<TR,P,0,N,D1,D2>::run(f1re,f1im,f2re,f2im,ar2,ai2);
        op[P*256] = make_ulonglong2(ar2, ai2);
        if constexpr (P+1 < 2*L+1) PL2s<TR,P+1,D1,D2>::run(f1re,f1im,f2re,f2im,op);
    }
};

// --------------------- k1': TP -> |mid|^2 partials only --------------------
template<int TR>
__device__ __forceinline__ void do_tripn2(const u64* actp, int tid){
    constexpr int L1 = kTL1(TR), L2 = kTL2(TR);
    constexpr int D1 = 2*L1+1, D2 = 2*L2+1;
    const int t = tid>>4, s = tid&15;
    u64 nsq2 = 0ULL;
    #pragma unroll
    for (int j=0;j<2;++j){
        const u64* ap = actp + j*512;
        u64 f1re[D1], f1im[D1], f2re[D2], f2im[D2];
        #pragma unroll
        for (int i=0;i<D1;++i){
            int idx = (kInOff(L1) + t*D1 + i)*2;
            f1re[i] = ap[idx]; f1im[i] = ap[idx+1];
        }
        #pragma unroll
        for (int i=0;i<D2;++i){
            int idx = (kInOff(L2) + s*D2 + i)*2;
            f2re[i] = ap[idx]; f2im[i] = ap[idx+1];
        }
        PL2n<TR,0,D1,D2>::run(f1re,f1im,f2re,f2im,nsq2);
    }
    float lo,hi; upk2(lo,hi,nsq2);
    g_part[(long)blockIdx.x*NCH + TR*256 + tid] = lo + hi;
}

template<int TR>
struct TripsN2 {
    static __device__ __forceinline__ void run(const u64* actp, int tid){
        do_tripn2<TR>(actp,tid);
        if constexpr (TR+1 < 23) TripsN2<TR+1>::run(actp,tid);
    }
};

__global__ void __launch_bounds__(256) k1_kernel(const float* __restrict__ act){
    __shared__ u64 actp[2*512];
    const int tid = threadIdx.x;
    const int b0  = blockIdx.x*4;
    for (int idx=tid; idx<1024; idx+=256){
        int j = idx>>9, i = idx&511;
        actp[idx] = pk2(act[(long)(b0+j)*512 + i], act[(long)(b0+j+2)*512 + i]);
    }
    __syncthreads();
    TripsN2<0>::run(actp, tid);
}

// ------------- k2a: reduce partials -> inverse (new_std + eps) ------------
__global__ void k2a_kernel(const float* __restrict__ bn){
    int c = blockIdx.x*256 + threadIdx.x;
    if (c >= NCH) return;
    int l = (c<1024)?0:((c<2560)?1:((c<4352)?2:3));
    float s[8];
    #pragma unroll
    for (int j=0;j<8;++j) s[j]=0.f;
    for (int i=0;i<NBLK1;i+=8){
        #pragma unroll
        for (int j=0;j<8;++j) s[j] += g_part[(long)(i+j)*NCH + c];
    }
    float t = 0.f;
    #pragma unroll
    for (int j=0;j<8;++j) t += s[j];
    float bstd = sqrtf(t / (2048.0f * (float)(2*l+1)));
    g_scale[c] = 1.0f/(0.5f*(bn[c] + bstd) + 1e-5f);
}

// --------------- k2b: fold scale into W, duplicated lanes ------------------
__global__ void k2b_kernel(const float* __restrict__ W){
    int r = blockIdx.x*256 + threadIdx.x;
    if (r >= 94208) return;
    int l = (r<16384)?0:((r<40960)?1:((r<69632)?2:3));
    int rr = r - kWBase(l);
    int c  = rr % kMLf(l);
    float sc = g_scale[kSOff(l) + c];
    float wr = W[2*r]*sc, wi = W[2*r+1]*sc;
    g_wrr[r] = pk2(wr, wr);
    g_wii[r] = pk2(wi, wi);
}

// ---------------- k3f: fused TP-recompute + complex GEMM -------------------
// 512 threads, 8 batches (4 packed pairs: j -> (b0+j, b0+j+4)) x one l.
// phase A: packed TP -> smem [(pair, p, c) -> (re2, im2)]  (two 256-thr halves)
// phase B: threads = cs(16 ch) x og(8: 2 o) x pair(4); per (it,p): one 16B LDS
//          feeds 8 fma2 (2 o x 4).
static constexpr int SMEM_MID_BYTES = 4*7*256*16;   // 114688
static constexpr int SMEM_ACT_OFF   = SMEM_MID_BYTES;
static constexpr int SMEM_TOTAL     = SMEM_MID_BYTES + 4*512*8; // 131072

template<int L,int TR>
__device__ __forceinline__ void phaseA2(const u64* actp, ulonglong2* smid, int tid){
    constexpr int L1 = kTL1(TR), L2 = kTL2(TR);
    constexpr int D1 = 2*L1+1, D2 = 2*L2+1;
    constexpr int DP = 2*L+1;
    const int ch   = tid & 255;
    const int t    = ch >> 4, s = ch & 15;
    const int half = tid >> 8;
    #pragma unroll
    for (int jj=0;jj<2;++jj){
        const int j = half*2 + jj;
        const u64* ap = actp + j*512;
        u64 f1re[D1], f1im[D1], f2re[D2], f2im[D2];
        #pragma unroll
        for (int i=0;i<D1;++i){
            int idx = (kInOff(L1) + t*D1 + i)*2;
            f1re[i] = ap[idx]; f1im[i] = ap[idx+1];
        }
        #pragma unroll
        for (int i=0;i<D2;++i){
            int idx = (kInOff(L2) + s*D2 + i)*2;
            f2re[i] = ap[idx]; f2im[i] = ap[idx+1];
        }
        PL2s<TR,0,D1,D2>::run(f1re,f1im,f2re,f2im, smid + (j*DP)*256 + ch);
    }
}

template<int L,int TR>
__device__ __forceinline__ void phaseB3(const ulonglong2* smid,
                                        u64 (&ar)[2][2*L+1], u64 (&ai)[2][2*L+1],
                                        int cs, int o0, int pair){
    constexpr int DP = 2*L+1;
    constexpr int ML = kMLf(L);
    constexpr int WB = kWBase(L);
    constexpr int TB = (TR - kTrip0(L))*256;
    const ulonglong2* mbase = smid + pair*(DP*256);
    const u64* wr0 = g_wrr + WB + (long)o0*ML + TB;
    const u64* wi0 = g_wii + WB + (long)o0*ML + TB;
    const u64* wr1 = wr0 + ML;
    const u64* wi1 = wi0 + ML;
    #pragma unroll 2
    for (int it=0; it<16; ++it){
        const int c = it*16 + cs;
        u64 wrA = ldg8(wr0 + c);
        u64 wiA = ldg8(wi0 + c);
        u64 wrB = ldg8(wr1 + c);
        u64 wiB = ldg8(wi1 + c);
        u64 wiAn = wiA ^ SGNMASK;
        u64 wiBn = wiB ^ SGNMASK;
        #pragma unroll
        for (int p=0;p<DP;++p){
            ulonglong2 m = mbase[p*256 + c];     // (re2, im2)
            ar[0][p] = fma2(wrA,  m.x, ar[0][p]);
            ar[0][p] = fma2(wiAn, m.y, ar[0][p]);
            ai[0][p] = fma2(wrA,  m.y, ai[0][p]);
            ai[0][p] = fma2(wiA,  m.x, ai[0][p]);
            ar[1][p] = fma2(wrB,  m.x, ar[1][p]);
            ar[1][p] = fma2(wiBn, m.y, ar[1][p]);
            ai[1][p] = fma2(wrB,  m.y, ai[1][p]);
            ai[1][p] = fma2(wiB,  m.x, ai[1][p]);
        }
    }
}

template<int L,int TR,int TREND>
struct TripF3 {
    static __device__ __forceinline__ void run(const u64* actp, ulonglong2* smid,
                                               u64 (&ar)[2][2*L+1], u64 (&ai)[2][2*L+1],
                                               int tid, int cs, int o0, int pair){
        phaseA2<L,TR>(actp, smid, tid);
        __syncthreads();
        phaseB3<L,TR>(smid, ar, ai, cs, o0, pair);
        __syncthreads();
        if constexpr (TR+1 < TREND)
            TripF3<L,TR+1,TREND>::run(actp,smid,ar,ai,tid,cs,o0,pair);
    }
};

template<int L>
__device__ __forceinline__ void k3body(const float* __restrict__ act, float* __restrict__ out,
                                       int bg, char* sm){
    constexpr int DP   = 2*L+1;
    constexpr int OROW = kInOff(L);
    ulonglong2* smid = reinterpret_cast<ulonglong2*>(sm);
    u64*        actp = reinterpret_cast<u64*>(sm + SMEM_ACT_OFF);

    const int tid = threadIdx.x;
    const int b0  = bg*8;

    // pack 8 batches into 4 batch-pair lanes: j -> (b0+j, b0+j+4)
    for (int idx=tid; idx<2048; idx+=512){
        int j = idx>>9, i = idx&511;
        actp[idx] = pk2(act[(long)(b0+j)*512 + i], act[(long)(b0+j+4)*512 + i]);
    }
    __syncthreads();

    const int cs   = tid & 15;
    const int og   = (tid>>4) & 7;
    const int pair = tid >> 7;
    const int o0   = og*2;

    u64 ar[2][DP], ai[2][DP];
    #pragma unroll
    for (int oi=0;oi<2;++oi)
        #pragma unroll
        for (int p=0;p<DP;++p){ ar[oi][p]=0ULL; ai[oi][p]=0ULL; }

    TripF3<L, kTrip0(L), kTrip0(L+1)>::run(actp, smid, ar, ai, tid, cs, o0, pair);

    // deterministic butterfly over cs (lane bits 0..3)
    #pragma unroll
    for (int oi=0;oi<2;++oi)
        #pragma unroll
        for (int p=0;p<DP;++p){
            u64 r = ar[oi][p], m = ai[oi][p];
            r = add2(r, __shfl_xor_sync(0xffffffffu, r, 1));
            m = add2(m, __shfl_xor_sync(0xffffffffu, m, 1));
            r = add2(r, __shfl_xor_sync(0xffffffffu, r, 2));
            m = add2(m, __shfl_xor_sync(0xffffffffu, m, 2));
            r = add2(r, __shfl_xor_sync(0xffffffffu, r, 4));
            m = add2(m, __shfl_xor_sync(0xffffffffu, m, 4));
            r = add2(r, __shfl_xor_sync(0xffffffffu, r, 8));
            m = add2(m, __shfl_xor_sync(0xffffffffu, m, 8));
            ar[oi][p]=r; ai[oi][p]=m;
        }

    if (cs == 0){
        #pragma unroll
        for (int oi=0;oi<2;++oi)
            #pragma unroll
            for (int p=0;p<DP;++p){
                float ra,rb,ia,ib;
                upk2(ra,rb,ar[oi][p]);
                upk2(ia,ib,ai[oi][p]);
                long rowA = (long)(b0+pair)*256   + OROW + (o0+oi)*DP + p;
                long rowB = (long)(b0+pair+4)*256 + OROW + (o0+oi)*DP + p;
                reinterpret_cast<float2*>(out)[rowA] = make_float2(ra,ia);
                reinterpret_cast<float2*>(out)[rowB] = make_float2(rb,ib);
            }
    }
}

__global__ void __launch_bounds__(512,1) k3f_kernel(const float* __restrict__ act,
                                                    float* __restrict__ out){
    extern __shared__ char sm[];
    const int bid = blockIdx.x;
    const int li  = bid >> 8;       // 0..3, longest l first
    const int bg  = bid & 255;
    switch (li){
        case 0: k3body<3>(act,out,bg,sm); break;
        case 1: k3body<2>(act,out,bg,sm); break;
        case 2: k3body<1>(act,out,bg,sm); break;
        default: k3body<0>(act,out,bg,sm); break;
    }
}

// --------------------------------- launch ---------------------------------
extern "C" void kernel_launch(void* const* d_in, const int* in_sizes, int n_in,
                              void* d_out, int out_size){
    const float* act = nullptr;
    const float* W   = nullptr;
    const float* bn  = nullptr;
    for (int i=0;i<n_in;++i){
        if      (in_sizes[i] == 1048576) act = (const float*)d_in[i];
        else if (in_sizes[i] == 188416)  W   = (const float*)d_in[i];
        else if (in_sizes[i] == 5888)    bn  = (const float*)d_in[i];
    }
    float* out = (float*)d_out;

    static bool attr_set = false;
    if (!attr_set){
        cudaFuncSetAttribute(k3f_kernel, cudaFuncAttributeMaxDynamicSharedMemorySize, SMEM_TOTAL);
        attr_set = true;
    }

    k1_kernel<<<512,256>>>(act);
    k2a_kernel<<<23,256>>>(bn);
    k2b_kernel<<<368,256>>>(W);
    k3f_kernel<<<1024,512,SMEM_TOTAL>>>(act, out);
}